// round 9
// baseline (speedup 1.0000x reference)
#include <cuda_runtime.h>
#include <cstdint>
#include <math.h>

#define T_TOK   2048
#define DIM     1024
#define NEXP    8
#define HID     4096
#define TOPK    2
#define MAXROWS (T_TOK * TOPK)   // 4096

// ---------------- scratch (__device__ globals) -------------------------------
__device__ float g_H[(size_t)MAXROWS * HID];   // 64 MB hidden acts (tf32)
__device__ float g_U[(size_t)T_TOK * DIM];     // 8 MB tf32-rounded inputs
__device__ float g_O[(size_t)MAXROWS * DIM];   // 16 MB expert outputs
__device__ int   g_rowmap[MAXROWS];            // slot -> token
__device__ int   g_counts[NEXP];
__device__ int   g_offsets[NEXP + 1];
__device__ int   g_tok_e[T_TOK * TOPK];
__device__ float g_tok_w[T_TOK * TOPK];
__device__ int   g_tok_slot[T_TOK * TOPK];
__device__ float g_dummy[1];

// ---------------- helpers ----------------------------------------------------
__device__ __forceinline__ uint32_t smem_u32(const void* p) {
    uint32_t a;
    asm("{ .reg .u64 t; cvta.to.shared.u64 t, %1; cvt.u32.u64 %0, t; }"
        : "=r"(a) : "l"(p));
    return a;
}
__device__ __forceinline__ float tf32r(float x) {
    float r;
    asm("cvt.rna.tf32.f32 %0, %1;" : "=f"(r) : "f"(x));
    return r;
}
__device__ __forceinline__ uint32_t tf32u(float x) {
    return __float_as_uint(tf32r(x));
}

#define CP16(dst, src) \
    asm volatile("cp.async.cg.shared.global [%0], [%1], 16;" :: "r"(dst), "l"(src))
#define CP_COMMIT()  asm volatile("cp.async.commit_group;" ::: "memory")
#define CP_WAIT1()   asm volatile("cp.async.wait_group 1;" ::: "memory")
#define CP_WAITALL() asm volatile("cp.async.wait_all;" ::: "memory")

#define LDSM_X4(r, addr) \
    asm volatile("ldmatrix.sync.aligned.m8n8.x4.shared.b16 {%0,%1,%2,%3}, [%4];" \
        : "=r"((r)[0]), "=r"((r)[1]), "=r"((r)[2]), "=r"((r)[3]) : "r"(addr))

#define MMA_TF32(d, a, b) \
    asm volatile("mma.sync.aligned.m16n8k8.row.col.f32.tf32.tf32.f32 " \
        "{%0,%1,%2,%3}, {%4,%5,%6,%7}, {%8,%9}, {%0,%1,%2,%3};" \
        : "+f"((d)[0]), "+f"((d)[1]), "+f"((d)[2]), "+f"((d)[3]) \
        : "r"((a)[0]), "r"((a)[1]), "r"((a)[2]), "r"((a)[3]), \
          "r"((b)[0]), "r"((b)[1]))

// ---------------- K0: round u -> g_U, reset counters -------------------------
__global__ void k_prep(const float* __restrict__ u)
{
    size_t i = ((size_t)blockIdx.x * blockDim.x + threadIdx.x) * 4;
    if (i < (size_t)T_TOK * DIM) {
        float4 v = *(const float4*)(u + i);
        v.x = tf32r(v.x); v.y = tf32r(v.y); v.z = tf32r(v.z); v.w = tf32r(v.w);
        *(float4*)(g_U + i) = v;
    }
    if (blockIdx.x == 0 && threadIdx.x < NEXP) g_counts[threadIdx.x] = 0;
}

// ---------------- K1: router -------------------------------------------------
__global__ void k_router(const float* __restrict__ u,
                         const float* __restrict__ cent,
                         const float* __restrict__ bias)
{
    int t    = blockIdx.x;
    int warp = threadIdx.x >> 5;
    int lane = threadIdx.x & 31;

    const float* ur = u + (size_t)t * DIM;
    const float* cr = cent + (size_t)warp * DIM;

    float s = 0.f;
    #pragma unroll 8
    for (int i = lane; i < DIM; i += 32) s += ur[i] * cr[i];
    #pragma unroll
    for (int o = 16; o; o >>= 1) s += __shfl_xor_sync(0xffffffffu, s, o);

    __shared__ float sc[NEXP];
    if (lane == 0) sc[warp] = s + bias[warp];
    __syncthreads();

    if (threadIdx.x == 0) {
        float m = sc[0];
        #pragma unroll
        for (int e = 1; e < NEXP; e++) m = fmaxf(m, sc[e]);
        float p[NEXP];
        float den = 0.f;
        #pragma unroll
        for (int e = 0; e < NEXP; e++) { p[e] = __expf(sc[e] - m); den += p[e]; }

        int e0 = 0;
        #pragma unroll
        for (int e = 1; e < NEXP; e++) if (p[e] > p[e0]) e0 = e;
        int e1 = (e0 == 0) ? 1 : 0;
        #pragma unroll
        for (int e = 0; e < NEXP; e++) if (e != e0 && p[e] > p[e1]) e1 = e;

        float inv = 1.f / den;
        g_tok_e[t * 2 + 0] = e0;  g_tok_w[t * 2 + 0] = p[e0] * inv;
        g_tok_e[t * 2 + 1] = e1;  g_tok_w[t * 2 + 1] = p[e1] * inv;
        atomicAdd(&g_counts[e0], 1);
        atomicAdd(&g_counts[e1], 1);
    }
}

// ---------------- K2: fused offsets + maxvio + scatter (single block) --------
__global__ void k_offscatter(float* __restrict__ maxvio_out)
{
    __shared__ int s_off[NEXP];
    __shared__ int s_cur[NEXP];
    int tid = threadIdx.x;
    if (tid < NEXP) s_cur[tid] = 0;
    if (tid == 0) {
        int off = 0, mx = 0;
        #pragma unroll
        for (int e = 0; e < NEXP; e++) {
            s_off[e] = off;
            g_offsets[e] = off;
            int c = g_counts[e];
            off += c;
            if (c > mx) mx = c;
        }
        g_offsets[NEXP] = off;
        const float perfect = (float)(TOPK * T_TOK) / (float)NEXP;
        *maxvio_out = ((float)mx - perfect) / perfect;
    }
    __syncthreads();
    for (int t = tid; t < T_TOK; t += blockDim.x) {
        #pragma unroll
        for (int k = 0; k < TOPK; k++) {
            int e = g_tok_e[t * 2 + k];
            int slot = s_off[e] + atomicAdd(&s_cur[e], 1);
            g_rowmap[slot] = t;
            g_tok_slot[t * 2 + k] = slot;
        }
    }
}

// ---------------- mma.sync tf32 grouped GEMM ---------------------------------
// Block 128x128, BK=32, 3-stage cp.async, 512 threads = 16 warps (4m x 4n),
// warp tile 32x32 (acc 32 regs/thread -> register headroom for frag pipelining).
// A via ldmatrix (pre-tf32 g_U / g_H). B via conflict-free scalar LDS + cvt
// from the natural n-major weight layout (no pre-transpose).
// IS_G2 == 0: g_H[slot] = relu_tf32(A @ W1[e] + b1[e])   (K=1024, N=4096)
// IS_G2 == 1: g_O[slot] = A @ W2[e]                       (K=4096, N=1024)
template<int IS_G2>
__global__ __launch_bounds__(512, 1) void k_gemm_mma(
    const float* __restrict__ Aglob,
    const float* __restrict__ Wglob,
    const float* __restrict__ bglob)
{
    constexpr int BM = 128, BN = 128, BK = 32, ST = 3;
    constexpr int LDA = BK + 4;               // 36 floats; ldmatrix conflict-free
    constexpr int LDB = BN + 8;               // 136 floats; LDS conflict-free
    constexpr int NLD   = IS_G2 ? DIM : HID;  // W leading dim / bias length
    constexpr int KTOT  = IS_G2 ? HID : DIM;
    constexpr int KCH   = KTOT / BK;
    constexpr int ALDIM = IS_G2 ? HID : DIM;
    constexpr int ABY = BM * LDA;             // floats per A stage (4608)
    constexpr int BBY = BK * LDB;             // floats per B stage (4352)

    extern __shared__ float sm[];
    float* s_bias = sm;                       // BN
    float* As     = sm + BN;                  // ST * ABY
    float* Bs     = As + ST * ABY;            // ST * BBY

    const int e    = blockIdx.z;
    const int base = g_offsets[e];
    const int cnt  = g_offsets[e + 1] - base;
    const int m0   = blockIdx.x * BM;
    if (m0 >= cnt) return;
    const int n0   = blockIdx.y * BN;

    const int tid  = threadIdx.x;
    const int lane = tid & 31, wid = tid >> 5;
    const int wm = wid & 3, wn = wid >> 2;    // 4 m-warps x 4 n-warps
    const int g = lane >> 2, tg = lane & 3;

    const float* W = Wglob + (size_t)e * (size_t)KTOT * NLD;

    if (!IS_G2 && tid < BN) s_bias[tid] = bglob[(size_t)e * NLD + n0 + tid];

    // per-thread cp.async slots: A (128 rows x 8 quads = 1024 -> 2/thread)
    const float* asrc[2];
    uint32_t     adst[2];
    #pragma unroll
    for (int j = 0; j < 2; j++) {
        int idx = tid + 512 * j;              // 0..1023
        int r = idx >> 3, kq = idx & 7;
        int slot = base + m0 + r;
        if (slot > MAXROWS - 1) slot = MAXROWS - 1;
        if (IS_G2) asrc[j] = Aglob + (size_t)slot * ALDIM + kq * 4;
        else       asrc[j] = Aglob + (size_t)g_rowmap[slot] * ALDIM + kq * 4;
        adst[j] = smem_u32(As + r * LDA + kq * 4);
    }
    // per-thread cp.async slots: B (32 k-rows x 32 n-quads = 1024 -> 2/thread)
    const float* bsrc[2];
    uint32_t     bdst[2];
    #pragma unroll
    for (int j = 0; j < 2; j++) {
        int idx = tid + 512 * j;
        int k = idx >> 5, nq = idx & 31;
        bsrc[j] = W + (size_t)k * NLD + n0 + nq * 4;
        bdst[j] = smem_u32(Bs + k * LDB + nq * 4);
    }

    // ldmatrix A base addresses (mi = 0..1)
    uint32_t amat[2];
    {
        int sector = lane >> 3, rowin = lane & 7;
        #pragma unroll
        for (int mi = 0; mi < 2; mi++) {
            int rloc = wm * 32 + mi * 16 + (sector & 1) * 8 + rowin;
            int colb = (sector >> 1) * 4;
            amat[mi] = smem_u32(As + rloc * LDA + colb);
        }
    }

    float acc[2][4][4] = {};

    // prologue: prefetch chunks 0 and 1
    #pragma unroll
    for (int pc = 0; pc < ST - 1; pc++) {
        const uint32_t soa = (uint32_t)(pc * ABY * 4);
        const uint32_t sob = (uint32_t)(pc * BBY * 4);
        const int k0 = pc * BK;
        #pragma unroll
        for (int j = 0; j < 2; j++) CP16(adst[j] + soa, asrc[j] + k0);
        #pragma unroll
        for (int j = 0; j < 2; j++) CP16(bdst[j] + sob, bsrc[j] + (size_t)k0 * NLD);
        CP_COMMIT();
    }

    for (int c = 0; c < KCH; c++) {
        CP_WAIT1();          // chunk c resident
        __syncthreads();

        const int wb = (c + ST - 1) % ST;
        if (c + ST - 1 < KCH) {
            const uint32_t soa = (uint32_t)(wb * ABY * 4);
            const uint32_t sob = (uint32_t)(wb * BBY * 4);
            const int k0 = (c + ST - 1) * BK;
            #pragma unroll
            for (int j = 0; j < 2; j++) CP16(adst[j] + soa, asrc[j] + k0);
            #pragma unroll
            for (int j = 0; j < 2; j++) CP16(bdst[j] + sob, bsrc[j] + (size_t)k0 * NLD);
        }
        CP_COMMIT();

        const int buf = c % ST;
        const float* Bb = Bs + buf * BBY;
        const uint32_t aoff = (uint32_t)(buf * ABY * 4);

        #pragma unroll
        for (int ks = 0; ks < 4; ks++) {
            const int kc = ks * 8 + tg;
            uint32_t au[2][4], bu[4][2];
            #pragma unroll
            for (int mi = 0; mi < 2; mi++)
                LDSM_X4(au[mi], amat[mi] + aoff + (uint32_t)(ks * 32));
            #pragma unroll
            for (int ni = 0; ni < 4; ni++) {
                const int bn = wn * 32 + ni * 8 + g;
                bu[ni][0] = tf32u(Bb[kc * LDB + bn]);
                bu[ni][1] = tf32u(Bb[(kc + 4) * LDB + bn]);
            }
            #pragma unroll
            for (int mi = 0; mi < 2; mi++)
                #pragma unroll
                for (int ni = 0; ni < 4; ni++)
                    MMA_TF32(acc[mi][ni], au[mi], bu[ni]);
        }
    }
    CP_WAITALL();

    // ---------------- epilogue ----------------
    #pragma unroll
    for (int mi = 0; mi < 2; mi++) {
        #pragma unroll
        for (int half = 0; half < 2; half++) {
            const int rl = wm * 32 + mi * 16 + half * 8 + g;
            if ((m0 + rl) >= cnt) continue;
            const int slot = base + m0 + rl;
            if (IS_G2) {
                float* orow = g_O + (size_t)slot * DIM + n0;
                #pragma unroll
                for (int ni = 0; ni < 4; ni++) {
                    const int cl = wn * 32 + ni * 8 + tg * 2;
                    float2 v;
                    v.x = acc[mi][ni][half * 2 + 0];
                    v.y = acc[mi][ni][half * 2 + 1];
                    *(float2*)(orow + cl) = v;
                }
            } else {
                float* hrow = g_H + (size_t)slot * HID + n0;
                #pragma unroll
                for (int ni = 0; ni < 4; ni++) {
                    const int cl = wn * 32 + ni * 8 + tg * 2;
                    float2 v;
                    v.x = tf32r(fmaxf(acc[mi][ni][half * 2 + 0] + s_bias[cl], 0.f));
                    v.y = tf32r(fmaxf(acc[mi][ni][half * 2 + 1] + s_bias[cl + 1], 0.f));
                    *(float2*)(hrow + cl) = v;
                }
            }
        }
    }
}

// ---------------- K5: combine out[t] = sum_k w_k * (o_k + b2[e_k]) ----------
__global__ void k_combine(const float* __restrict__ b2, float* __restrict__ out)
{
    int t = blockIdx.x;
    int d = threadIdx.x * 4;
    int e0 = g_tok_e[t * 2], e1 = g_tok_e[t * 2 + 1];
    float w0 = g_tok_w[t * 2], w1 = g_tok_w[t * 2 + 1];
    int s0 = g_tok_slot[t * 2], s1 = g_tok_slot[t * 2 + 1];

    float4 o0 = *(const float4*)(g_O + (size_t)s0 * DIM + d);
    float4 o1 = *(const float4*)(g_O + (size_t)s1 * DIM + d);
    float4 c0 = *(const float4*)(b2 + (size_t)e0 * DIM + d);
    float4 c1 = *(const float4*)(b2 + (size_t)e1 * DIM + d);

    float4 r;
    r.x = w0 * (o0.x + c0.x) + w1 * (o1.x + c1.x);
    r.y = w0 * (o0.y + c0.y) + w1 * (o1.y + c1.y);
    r.z = w0 * (o0.z + c0.z) + w1 * (o1.z + c1.z);
    r.w = w0 * (o0.w + c0.w) + w1 * (o1.w + c1.w);
    *(float4*)(out + (size_t)t * DIM + d) = r;
}

// ---------------- launch -----------------------------------------------------
extern "C" void kernel_launch(void* const* d_in, const int* in_sizes, int n_in,
                              void* d_out, int out_size)
{
    const float* u    = (const float*)d_in[0];
    const float* cent = (const float*)d_in[1];
    const float* bias = (const float*)d_in[2];
    const float* W1   = (const float*)d_in[3];
    const float* b1   = (const float*)d_in[4];
    const float* W2   = (const float*)d_in[5];
    const float* b2   = (const float*)d_in[6];
    float* out = (float*)d_out;

    float* maxvio_ptr;
    if (out_size > T_TOK * DIM) {
        maxvio_ptr = out + (size_t)T_TOK * DIM;
    } else {
        cudaGetSymbolAddress((void**)&maxvio_ptr, g_dummy);
    }
    float* uruf;  cudaGetSymbolAddress((void**)&uruf, g_U);
    float* hbuf;  cudaGetSymbolAddress((void**)&hbuf, g_H);

    // smem: 128 + 3*(128*36 + 32*136) floats = 128 + 26880 = 27008 -> 108032 B
    const int SMEM = 27008 * 4;
    cudaFuncSetAttribute(k_gemm_mma<0>, cudaFuncAttributeMaxDynamicSharedMemorySize, SMEM);
    cudaFuncSetAttribute(k_gemm_mma<1>, cudaFuncAttributeMaxDynamicSharedMemorySize, SMEM);

    k_prep<<<(T_TOK * DIM / 4 + 255) / 256, 256>>>(u);           // idx 0
    k_router<<<T_TOK, 256>>>(u, cent, bias);                     // idx 1
    k_offscatter<<<1, 1024>>>(maxvio_ptr);                       // idx 2
    k_gemm_mma<0><<<dim3(16, HID / 128, NEXP), 512, SMEM>>>(uruf, W1, b1);  // idx 3
    k_gemm_mma<1><<<dim3(16, DIM / 128, NEXP), 512, SMEM>>>(hbuf, W2, b2);  // idx 4
    k_combine<<<T_TOK, 256>>>(b2, out);                          // idx 5
}

// round 10
// speedup vs baseline: 1.1373x; 1.1373x over previous
#include <cuda_runtime.h>
#include <cstdint>
#include <math.h>

#define T_TOK   2048
#define DIM     1024
#define NEXP    8
#define HID     4096
#define TOPK    2
#define MAXROWS (T_TOK * TOPK)   // 4096

// ---------------- scratch (__device__ globals) -------------------------------
__device__ float g_H[(size_t)MAXROWS * HID];   // 64 MB hidden acts (tf32)
__device__ float g_U[(size_t)T_TOK * DIM];     // 8 MB tf32-rounded inputs
__device__ float g_O[(size_t)MAXROWS * DIM];   // 16 MB expert outputs
__device__ int   g_rowmap[MAXROWS];            // slot -> token
__device__ int   g_counts[NEXP];
__device__ int   g_offsets[NEXP + 1];
__device__ int   g_tok_e[T_TOK * TOPK];
__device__ float g_tok_w[T_TOK * TOPK];
__device__ int   g_tok_slot[T_TOK * TOPK];
__device__ float g_dummy[1];

// ---------------- helpers ----------------------------------------------------
__device__ __forceinline__ uint32_t smem_u32(const void* p) {
    uint32_t a;
    asm("{ .reg .u64 t; cvta.to.shared.u64 t, %1; cvt.u32.u64 %0, t; }"
        : "=r"(a) : "l"(p));
    return a;
}
__device__ __forceinline__ float tf32r(float x) {
    float r;
    asm("cvt.rna.tf32.f32 %0, %1;" : "=f"(r) : "f"(x));
    return r;
}

#define CP16(dst, src) \
    asm volatile("cp.async.cg.shared.global [%0], [%1], 16;" :: "r"(dst), "l"(src))
#define CP_COMMIT()  asm volatile("cp.async.commit_group;" ::: "memory")
#define CP_WAIT1()   asm volatile("cp.async.wait_group 1;" ::: "memory")
#define CP_WAITALL() asm volatile("cp.async.wait_all;" ::: "memory")

#define LDSM_X4(r, addr) \
    asm volatile("ldmatrix.sync.aligned.m8n8.x4.shared.b16 {%0,%1,%2,%3}, [%4];" \
        : "=r"((r)[0]), "=r"((r)[1]), "=r"((r)[2]), "=r"((r)[3]) : "r"(addr))

#define MMA_TF32(d, a, b) \
    asm volatile("mma.sync.aligned.m16n8k8.row.col.f32.tf32.tf32.f32 " \
        "{%0,%1,%2,%3}, {%4,%5,%6,%7}, {%8,%9}, {%0,%1,%2,%3};" \
        : "+f"((d)[0]), "+f"((d)[1]), "+f"((d)[2]), "+f"((d)[3]) \
        : "r"((a)[0]), "r"((a)[1]), "r"((a)[2]), "r"((a)[3]), \
          "r"((b)[0]), "r"((b)[1]))

// ---------------- K0: round u -> g_U, reset counters -------------------------
__global__ void k_prep(const float* __restrict__ u)
{
    size_t i = ((size_t)blockIdx.x * blockDim.x + threadIdx.x) * 4;
    if (i < (size_t)T_TOK * DIM) {
        float4 v = *(const float4*)(u + i);
        v.x = tf32r(v.x); v.y = tf32r(v.y); v.z = tf32r(v.z); v.w = tf32r(v.w);
        *(float4*)(g_U + i) = v;
    }
    if (blockIdx.x == 0 && threadIdx.x < NEXP) g_counts[threadIdx.x] = 0;
}

// ---------------- K1: router -------------------------------------------------
__global__ void k_router(const float* __restrict__ u,
                         const float* __restrict__ cent,
                         const float* __restrict__ bias)
{
    int t    = blockIdx.x;
    int warp = threadIdx.x >> 5;
    int lane = threadIdx.x & 31;

    const float* ur = u + (size_t)t * DIM;
    const float* cr = cent + (size_t)warp * DIM;

    float s = 0.f;
    #pragma unroll 8
    for (int i = lane; i < DIM; i += 32) s += ur[i] * cr[i];
    #pragma unroll
    for (int o = 16; o; o >>= 1) s += __shfl_xor_sync(0xffffffffu, s, o);

    __shared__ float sc[NEXP];
    if (lane == 0) sc[warp] = s + bias[warp];
    __syncthreads();

    if (threadIdx.x == 0) {
        float m = sc[0];
        #pragma unroll
        for (int e = 1; e < NEXP; e++) m = fmaxf(m, sc[e]);
        float p[NEXP];
        float den = 0.f;
        #pragma unroll
        for (int e = 0; e < NEXP; e++) { p[e] = __expf(sc[e] - m); den += p[e]; }

        int e0 = 0;
        #pragma unroll
        for (int e = 1; e < NEXP; e++) if (p[e] > p[e0]) e0 = e;
        int e1 = (e0 == 0) ? 1 : 0;
        #pragma unroll
        for (int e = 0; e < NEXP; e++) if (e != e0 && p[e] > p[e1]) e1 = e;

        float inv = 1.f / den;
        g_tok_e[t * 2 + 0] = e0;  g_tok_w[t * 2 + 0] = p[e0] * inv;
        g_tok_e[t * 2 + 1] = e1;  g_tok_w[t * 2 + 1] = p[e1] * inv;
        atomicAdd(&g_counts[e0], 1);
        atomicAdd(&g_counts[e1], 1);
    }
}

// ---------------- K2: fused offsets + maxvio + scatter (single block) --------
__global__ void k_offscatter(float* __restrict__ maxvio_out)
{
    __shared__ int s_off[NEXP];
    __shared__ int s_cur[NEXP];
    int tid = threadIdx.x;
    if (tid < NEXP) s_cur[tid] = 0;
    if (tid == 0) {
        int off = 0, mx = 0;
        #pragma unroll
        for (int e = 0; e < NEXP; e++) {
            s_off[e] = off;
            g_offsets[e] = off;
            int c = g_counts[e];
            off += c;
            if (c > mx) mx = c;
        }
        g_offsets[NEXP] = off;
        const float perfect = (float)(TOPK * T_TOK) / (float)NEXP;
        *maxvio_out = ((float)mx - perfect) / perfect;
    }
    __syncthreads();
    for (int t = tid; t < T_TOK; t += blockDim.x) {
        #pragma unroll
        for (int k = 0; k < TOPK; k++) {
            int e = g_tok_e[t * 2 + k];
            int slot = s_off[e] + atomicAdd(&s_cur[e], 1);
            g_rowmap[slot] = t;
            g_tok_slot[t * 2 + k] = slot;
        }
    }
}

// ---------------- mma.sync tf32 grouped GEMM ---------------------------------
// Block 128x128, BK=32, 256 threads, 8 warps (2m x 4n), warp tile 64x32.
// A: pre-tf32 g_U/g_H via cp.async ST=3 + ldmatrix (round-5 path, unchanged).
// B: k-pair smem layout Bq[r=4ks+tg][n] = {B[8ks+tg][n], B[8ks+tg+4][n]},
//    built by LDG->cvt->STS.128 with 2-chunk register staging. Inner loop
//    per ks: 4 LDSM + 4 LDS.64 + 16 MMA (no cvt, no scalar LDS).
// IS_G2 == 0: g_H[slot] = relu_tf32(A @ W1[e] + b1[e])   (K=1024, N=4096)
// IS_G2 == 1: g_O[slot] = A @ W2[e]                       (K=4096, N=1024)
template<int IS_G2>
__global__ __launch_bounds__(256, 2) void k_gemm_mma(
    const float* __restrict__ Aglob,
    const float* __restrict__ Wglob,
    const float* __restrict__ bglob)
{
    constexpr int BM = 128, BN = 128, BK = 32, ST = 3;
    constexpr int LDA = BK + 4;               // 36 floats; ldmatrix conflict-free
    constexpr int LDP = 264;                  // floats per B pair-row (128 fl2 + pad)
    constexpr int NLD   = IS_G2 ? DIM : HID;  // W leading dim / bias length
    constexpr int KTOT  = IS_G2 ? HID : DIM;
    constexpr int KCH   = KTOT / BK;
    constexpr int ALDIM = IS_G2 ? HID : DIM;
    constexpr int ABY = BM * LDA;             // floats per A stage (4608)
    constexpr int BPY = 16 * LDP;             // floats per B stage (4224)

    extern __shared__ float sm[];
    float* s_bias = sm;                       // BN
    float* As     = sm + BN;                  // ST * ABY
    float* Bq     = As + ST * ABY;            // 2 * BPY

    const int e    = blockIdx.z;
    const int base = g_offsets[e];
    const int cnt  = g_offsets[e + 1] - base;
    const int m0   = blockIdx.x * BM;
    if (m0 >= cnt) return;
    const int n0   = blockIdx.y * BN;

    const int tid  = threadIdx.x;
    const int lane = tid & 31, wid = tid >> 5;
    const int wm = wid & 1, wn = wid >> 1;    // 2 m-warps x 4 n-warps
    const int g = lane >> 2, tg = lane & 3;

    const float* W = Wglob + (size_t)e * (size_t)KTOT * NLD;

    if (!IS_G2 && tid < BN) s_bias[tid] = bglob[(size_t)e * NLD + n0 + tid];

    // per-thread cp.async slots: A (128 rows x 8 quads = 1024 -> 4/thread)
    const float* asrc[4];
    uint32_t     adst[4];
    #pragma unroll
    for (int j = 0; j < 4; j++) {
        int idx = tid + 256 * j;              // 0..1023
        int r = idx >> 3, kq = idx & 7;
        int slot = base + m0 + r;
        if (slot > MAXROWS - 1) slot = MAXROWS - 1;
        if (IS_G2) asrc[j] = Aglob + (size_t)slot * ALDIM + kq * 4;
        else       asrc[j] = Aglob + (size_t)g_rowmap[slot] * ALDIM + kq * 4;
        adst[j] = smem_u32(As + r * LDA + kq * 4);
    }

    // B pair-load mapping: warp w covers ks = w&3, n-block m = (w>>2) + 2j
    // lane: bb = lane&3 (k-offset within quad), g8 = lane>>2 (n-quad within block)
    const int ksb = wid & 3;
    const int mhi = wid >> 2;
    const int bb  = lane & 3;
    const int g8  = lane >> 2;
    const int rrow = 4 * ksb + bb;            // pair-row index (0..15)
    const float* bptr[2];                     // row k = 8*ksb + bb, col base
    int          bsoff[2];                    // smem float offset within stage
    #pragma unroll
    for (int j = 0; j < 2; j++) {
        int m  = mhi + 2 * j;                 // 0..3
        int nq = g8 + 8 * m;                  // n-quad 0..31
        bptr[j]  = W + (size_t)(8 * ksb + bb) * NLD + n0 + nq * 4;
        bsoff[j] = rrow * LDP + nq * 8;       // fl2 index nq*4 -> float offset *2
    }
    float4 sva[2], svb[2];                    // staging regs (chunk c+2)

    // ldmatrix A base addresses (mi = 0..3)
    uint32_t amat[4];
    {
        int sector = lane >> 3, rowin = lane & 7;
        #pragma unroll
        for (int mi = 0; mi < 4; mi++) {
            int rloc = wm * 64 + mi * 16 + (sector & 1) * 8 + rowin;
            int colb = (sector >> 1) * 4;
            amat[mi] = smem_u32(As + rloc * LDA + colb);
        }
    }

    float acc[4][4][4] = {};

    // ---- prologue ----
    // B chunk 0 -> regs -> smem buf0; B chunk 1 -> regs (stored at c=0)
    #pragma unroll
    for (int j = 0; j < 2; j++) {
        sva[j] = __ldg((const float4*)(bptr[j]));
        svb[j] = __ldg((const float4*)(bptr[j] + 4 * NLD));
    }
    #pragma unroll
    for (int j = 0; j < 2; j++) {
        float4 lo = make_float4(tf32r(sva[j].x), tf32r(svb[j].x),
                                tf32r(sva[j].y), tf32r(svb[j].y));
        float4 hi = make_float4(tf32r(sva[j].z), tf32r(svb[j].z),
                                tf32r(sva[j].w), tf32r(svb[j].w));
        *(float4*)(Bq + bsoff[j])     = lo;
        *(float4*)(Bq + bsoff[j] + 4) = hi;
    }
    #pragma unroll
    for (int j = 0; j < 2; j++) {
        sva[j] = __ldg((const float4*)(bptr[j] + (size_t)BK * NLD));
        svb[j] = __ldg((const float4*)(bptr[j] + (size_t)(BK + 4) * NLD));
    }
    // A chunks 0 and 1 via cp.async
    #pragma unroll
    for (int pc = 0; pc < ST - 1; pc++) {
        const uint32_t soa = (uint32_t)(pc * ABY * 4);
        const int k0 = pc * BK;
        #pragma unroll
        for (int j = 0; j < 4; j++) CP16(adst[j] + soa, asrc[j] + k0);
        CP_COMMIT();
    }

    for (int c = 0; c < KCH; c++) {
        CP_WAIT1();          // A chunk c resident
        __syncthreads();     // + all warps done reading bufs from chunk c-1

        // store staged B (chunk c+1) into buffer (c+1)&1
        if (c + 1 < KCH) {
            float* Bd = Bq + ((c + 1) & 1) * BPY;
            #pragma unroll
            for (int j = 0; j < 2; j++) {
                float4 lo = make_float4(tf32r(sva[j].x), tf32r(svb[j].x),
                                        tf32r(sva[j].y), tf32r(svb[j].y));
                float4 hi = make_float4(tf32r(sva[j].z), tf32r(svb[j].z),
                                        tf32r(sva[j].w), tf32r(svb[j].w));
                *(float4*)(Bd + bsoff[j])     = lo;
                *(float4*)(Bd + bsoff[j] + 4) = hi;
            }
        }
        // A cp.async for chunk c+2
        if (c + ST - 1 < KCH) {
            const int wb = (c + ST - 1) % ST;
            const uint32_t soa = (uint32_t)(wb * ABY * 4);
            const int k0 = (c + ST - 1) * BK;
            #pragma unroll
            for (int j = 0; j < 4; j++) CP16(adst[j] + soa, asrc[j] + k0);
        }
        CP_COMMIT();
        // B LDG for chunk c+2 into staging regs
        if (c + 2 < KCH) {
            const size_t k0 = (size_t)(c + 2) * BK;
            #pragma unroll
            for (int j = 0; j < 2; j++) {
                sva[j] = __ldg((const float4*)(bptr[j] + k0 * NLD));
                svb[j] = __ldg((const float4*)(bptr[j] + (k0 + 4) * NLD));
            }
        }

        const uint32_t aoff = (uint32_t)((c % ST) * ABY * 4);
        const float* Bb = Bq + (c & 1) * BPY;

        #pragma unroll
        for (int ks = 0; ks < 4; ks++) {
            uint32_t au[4][4], bu[4][2];
            #pragma unroll
            for (int mi = 0; mi < 4; mi++)
                LDSM_X4(au[mi], amat[mi] + aoff + (uint32_t)(ks * 32));
            const float* brow = Bb + (4 * ks + tg) * LDP + wn * 64 + g * 2;
            #pragma unroll
            for (int ni = 0; ni < 4; ni++) {
                float2 p = *(const float2*)(brow + ni * 16);
                bu[ni][0] = __float_as_uint(p.x);
                bu[ni][1] = __float_as_uint(p.y);
            }
            #pragma unroll
            for (int mi = 0; mi < 4; mi++)
                #pragma unroll
                for (int ni = 0; ni < 4; ni++)
                    MMA_TF32(acc[mi][ni], au[mi], bu[ni]);
        }
    }
    CP_WAITALL();

    // ---------------- epilogue ----------------
    #pragma unroll
    for (int mi = 0; mi < 4; mi++) {
        #pragma unroll
        for (int half = 0; half < 2; half++) {
            const int rl = wm * 64 + mi * 16 + half * 8 + g;
            if ((m0 + rl) >= cnt) continue;
            const int slot = base + m0 + rl;
            if (IS_G2) {
                float* orow = g_O + (size_t)slot * DIM + n0;
                #pragma unroll
                for (int ni = 0; ni < 4; ni++) {
                    const int cl = wn * 32 + ni * 8 + tg * 2;
                    float2 v;
                    v.x = acc[mi][ni][half * 2 + 0];
                    v.y = acc[mi][ni][half * 2 + 1];
                    *(float2*)(orow + cl) = v;
                }
            } else {
                float* hrow = g_H + (size_t)slot * HID + n0;
                #pragma unroll
                for (int ni = 0; ni < 4; ni++) {
                    const int cl = wn * 32 + ni * 8 + tg * 2;
                    float2 v;
                    v.x = tf32r(fmaxf(acc[mi][ni][half * 2 + 0] + s_bias[cl], 0.f));
                    v.y = tf32r(fmaxf(acc[mi][ni][half * 2 + 1] + s_bias[cl + 1], 0.f));
                    *(float2*)(hrow + cl) = v;
                }
            }
        }
    }
}

// ---------------- K5: combine out[t] = sum_k w_k * (o_k + b2[e_k]) ----------
__global__ void k_combine(const float* __restrict__ b2, float* __restrict__ out)
{
    int t = blockIdx.x;
    int d = threadIdx.x * 4;
    int e0 = g_tok_e[t * 2], e1 = g_tok_e[t * 2 + 1];
    float w0 = g_tok_w[t * 2], w1 = g_tok_w[t * 2 + 1];
    int s0 = g_tok_slot[t * 2], s1 = g_tok_slot[t * 2 + 1];

    float4 o0 = *(const float4*)(g_O + (size_t)s0 * DIM + d);
    float4 o1 = *(const float4*)(g_O + (size_t)s1 * DIM + d);
    float4 c0 = *(const float4*)(b2 + (size_t)e0 * DIM + d);
    float4 c1 = *(const float4*)(b2 + (size_t)e1 * DIM + d);

    float4 r;
    r.x = w0 * (o0.x + c0.x) + w1 * (o1.x + c1.x);
    r.y = w0 * (o0.y + c0.y) + w1 * (o1.y + c1.y);
    r.z = w0 * (o0.z + c0.z) + w1 * (o1.z + c1.z);
    r.w = w0 * (o0.w + c0.w) + w1 * (o1.w + c1.w);
    *(float4*)(out + (size_t)t * DIM + d) = r;
}

// ---------------- launch -----------------------------------------------------
extern "C" void kernel_launch(void* const* d_in, const int* in_sizes, int n_in,
                              void* d_out, int out_size)
{
    const float* u    = (const float*)d_in[0];
    const float* cent = (const float*)d_in[1];
    const float* bias = (const float*)d_in[2];
    const float* W1   = (const float*)d_in[3];
    const float* b1   = (const float*)d_in[4];
    const float* W2   = (const float*)d_in[5];
    const float* b2   = (const float*)d_in[6];
    float* out = (float*)d_out;

    float* maxvio_ptr;
    if (out_size > T_TOK * DIM) {
        maxvio_ptr = out + (size_t)T_TOK * DIM;
    } else {
        cudaGetSymbolAddress((void**)&maxvio_ptr, g_dummy);
    }
    float* uruf;  cudaGetSymbolAddress((void**)&uruf, g_U);
    float* hbuf;  cudaGetSymbolAddress((void**)&hbuf, g_H);

    // smem: 128 + 3*4608 (A) + 2*4224 (B pairs) = 22400 floats = 89600 B
    const int SMEM = 22400 * 4;
    cudaFuncSetAttribute(k_gemm_mma<0>, cudaFuncAttributeMaxDynamicSharedMemorySize, SMEM);
    cudaFuncSetAttribute(k_gemm_mma<1>, cudaFuncAttributeMaxDynamicSharedMemorySize, SMEM);

    k_prep<<<(T_TOK * DIM / 4 + 255) / 256, 256>>>(u);           // idx 0
    k_router<<<T_TOK, 256>>>(u, cent, bias);                     // idx 1
    k_offscatter<<<1, 1024>>>(maxvio_ptr);                       // idx 2
    k_gemm_mma<0><<<dim3(16, HID / 128, NEXP), 256, SMEM>>>(uruf, W1, b1);  // idx 3
    k_gemm_mma<1><<<dim3(16, DIM / 128, NEXP), 256, SMEM>>>(hbuf, W2, b2);  // idx 4
    k_combine<<<T_TOK, 256>>>(b2, out);                          // idx 5
}

// round 11
// speedup vs baseline: 1.1666x; 1.0258x over previous
#include <cuda_runtime.h>
#include <cstdint>
#include <math.h>

#define T_TOK   2048
#define DIM     1024
#define NEXP    8
#define HID     4096
#define TOPK    2
#define MAXROWS (T_TOK * TOPK)   // 4096
#define W1ELEM  ((size_t)NEXP * DIM * HID)   // 33.55M
#define W2ELEM  ((size_t)NEXP * HID * DIM)   // 33.55M

// ---------------- scratch (__device__ globals) -------------------------------
__device__ float g_H[(size_t)MAXROWS * HID];   // 64 MB hidden acts (tf32)
__device__ float g_U[(size_t)T_TOK * DIM];     // 8 MB tf32-rounded inputs
__device__ float g_O[(size_t)MAXROWS * DIM];   // 16 MB expert outputs
__device__ float g_W1r[W1ELEM];                // 134 MB tf32-rounded W1 (same layout)
__device__ float g_W2r[W2ELEM];                // 134 MB tf32-rounded W2 (same layout)
__device__ int   g_rowmap[MAXROWS];            // slot -> token
__device__ int   g_counts[NEXP];
__device__ int   g_offsets[NEXP + 1];
__device__ int   g_tok_e[T_TOK * TOPK];
__device__ float g_tok_w[T_TOK * TOPK];
__device__ int   g_tok_slot[T_TOK * TOPK];
__device__ float g_dummy[1];

// ---------------- helpers ----------------------------------------------------
__device__ __forceinline__ uint32_t smem_u32(const void* p) {
    uint32_t a;
    asm("{ .reg .u64 t; cvta.to.shared.u64 t, %1; cvt.u32.u64 %0, t; }"
        : "=r"(a) : "l"(p));
    return a;
}
__device__ __forceinline__ float tf32r(float x) {
    float r;
    asm("cvt.rna.tf32.f32 %0, %1;" : "=f"(r) : "f"(x));
    return r;
}

#define CP16(dst, src) \
    asm volatile("cp.async.cg.shared.global [%0], [%1], 16;" :: "r"(dst), "l"(src))
#define CP_COMMIT()  asm volatile("cp.async.commit_group;" ::: "memory")
#define CP_WAIT1()   asm volatile("cp.async.wait_group 1;" ::: "memory")
#define CP_WAITALL() asm volatile("cp.async.wait_all;" ::: "memory")

#define LDSM_X4(r, addr) \
    asm volatile("ldmatrix.sync.aligned.m8n8.x4.shared.b16 {%0,%1,%2,%3}, [%4];" \
        : "=r"((r)[0]), "=r"((r)[1]), "=r"((r)[2]), "=r"((r)[3]) : "r"(addr))

#define MMA_TF32(d, a, b) \
    asm volatile("mma.sync.aligned.m16n8k8.row.col.f32.tf32.tf32.f32 " \
        "{%0,%1,%2,%3}, {%4,%5,%6,%7}, {%8,%9}, {%0,%1,%2,%3};" \
        : "+f"((d)[0]), "+f"((d)[1]), "+f"((d)[2]), "+f"((d)[3]) \
        : "r"((a)[0]), "r"((a)[1]), "r"((a)[2]), "r"((a)[3]), \
          "r"((b)[0]), "r"((b)[1]))

// ---------------- K0: round u -> g_U and W1 -> g_W1r, reset counters ---------
__global__ void k_prep(const float* __restrict__ u, const float* __restrict__ W1)
{
    const size_t U4 = (size_t)T_TOK * DIM / 4;
    const size_t W4 = W1ELEM / 4;
    size_t i = (size_t)blockIdx.x * blockDim.x + threadIdx.x;
    if (i < U4) {
        float4 v = *(const float4*)(u + i * 4);
        v.x = tf32r(v.x); v.y = tf32r(v.y); v.z = tf32r(v.z); v.w = tf32r(v.w);
        *(float4*)(g_U + i * 4) = v;
    } else if (i < U4 + W4) {
        size_t j = i - U4;
        float4 v = *(const float4*)(W1 + j * 4);
        v.x = tf32r(v.x); v.y = tf32r(v.y); v.z = tf32r(v.z); v.w = tf32r(v.w);
        *(float4*)(g_W1r + j * 4) = v;
    }
    if (blockIdx.x == 0 && threadIdx.x < NEXP) g_counts[threadIdx.x] = 0;
}

// ---------------- K1: router -------------------------------------------------
__global__ void k_router(const float* __restrict__ u,
                         const float* __restrict__ cent,
                         const float* __restrict__ bias)
{
    int t    = blockIdx.x;
    int warp = threadIdx.x >> 5;
    int lane = threadIdx.x & 31;

    const float* ur = u + (size_t)t * DIM;
    const float* cr = cent + (size_t)warp * DIM;

    float s = 0.f;
    #pragma unroll 8
    for (int i = lane; i < DIM; i += 32) s += ur[i] * cr[i];
    #pragma unroll
    for (int o = 16; o; o >>= 1) s += __shfl_xor_sync(0xffffffffu, s, o);

    __shared__ float sc[NEXP];
    if (lane == 0) sc[warp] = s + bias[warp];
    __syncthreads();

    if (threadIdx.x == 0) {
        float m = sc[0];
        #pragma unroll
        for (int e = 1; e < NEXP; e++) m = fmaxf(m, sc[e]);
        float p[NEXP];
        float den = 0.f;
        #pragma unroll
        for (int e = 0; e < NEXP; e++) { p[e] = __expf(sc[e] - m); den += p[e]; }

        int e0 = 0;
        #pragma unroll
        for (int e = 1; e < NEXP; e++) if (p[e] > p[e0]) e0 = e;
        int e1 = (e0 == 0) ? 1 : 0;
        #pragma unroll
        for (int e = 0; e < NEXP; e++) if (e != e0 && p[e] > p[e1]) e1 = e;

        float inv = 1.f / den;
        g_tok_e[t * 2 + 0] = e0;  g_tok_w[t * 2 + 0] = p[e0] * inv;
        g_tok_e[t * 2 + 1] = e1;  g_tok_w[t * 2 + 1] = p[e1] * inv;
        atomicAdd(&g_counts[e0], 1);
        atomicAdd(&g_counts[e1], 1);
    }
}

// ---------------- K2: fused offsets + maxvio + scatter (single block) --------
__global__ void k_offscatter(float* __restrict__ maxvio_out)
{
    __shared__ int s_off[NEXP];
    __shared__ int s_cur[NEXP];
    int tid = threadIdx.x;
    if (tid < NEXP) s_cur[tid] = 0;
    if (tid == 0) {
        int off = 0, mx = 0;
        #pragma unroll
        for (int e = 0; e < NEXP; e++) {
            s_off[e] = off;
            g_offsets[e] = off;
            int c = g_counts[e];
            off += c;
            if (c > mx) mx = c;
        }
        g_offsets[NEXP] = off;
        const float perfect = (float)(TOPK * T_TOK) / (float)NEXP;
        *maxvio_out = ((float)mx - perfect) / perfect;
    }
    __syncthreads();
    for (int t = tid; t < T_TOK; t += blockDim.x) {
        #pragma unroll
        for (int k = 0; k < TOPK; k++) {
            int e = g_tok_e[t * 2 + k];
            int slot = s_off[e] + atomicAdd(&s_cur[e], 1);
            g_rowmap[slot] = t;
            g_tok_slot[t * 2 + k] = slot;
        }
    }
}

// ---------------- mma.sync tf32 grouped GEMM ---------------------------------
// Round-5 structure: block 128x128, BK=32, 3-stage cp.async, 8 warps (2m x 4n),
// warp tile 64x32, LDB=136 conflict-free scalar B loads. Weights PRE-ROUNDED
// to tf32 (g_W1r / g_W2r) so the inner loop has ZERO cvt (28 slots per ks,
// was 36). GEMM1 additionally rounds W2 -> g_W2r in its tail (every CTA
// handles a static 2048-float4 chunk; ~3/4 of CTAs are routing-idle anyway).
// IS_G2 == 0: g_H[slot] = relu_tf32(A @ W1r[e] + b1[e])   (K=1024, N=4096)
// IS_G2 == 1: g_O[slot] = A @ W2r[e]                       (K=4096, N=1024)
template<int IS_G2>
__global__ __launch_bounds__(256, 2) void k_gemm_mma(
    const float* __restrict__ Aglob,
    const float* __restrict__ Wglob,
    const float* __restrict__ bglob,
    const float* __restrict__ W2src)
{
    constexpr int BM = 128, BN = 128, BK = 32, ST = 3;
    constexpr int LDA = BK + 4;               // 36 floats; ldmatrix conflict-free
    constexpr int LDB = BN + 8;               // 136 floats; LDS conflict-free
    constexpr int NLD   = IS_G2 ? DIM : HID;  // W leading dim / bias length
    constexpr int KTOT  = IS_G2 ? HID : DIM;
    constexpr int KCH   = KTOT / BK;
    constexpr int ALDIM = IS_G2 ? HID : DIM;
    constexpr int ABY = BM * LDA;             // floats per A stage
    constexpr int BBY = BK * LDB;             // floats per B stage

    extern __shared__ float sm[];
    float* s_bias = sm;                       // BN
    float* As     = sm + BN;                  // ST * ABY
    float* Bs     = As + ST * ABY;            // ST * BBY

    const int e    = blockIdx.z;
    const int base = g_offsets[e];
    const int cnt  = g_offsets[e + 1] - base;
    const int m0   = blockIdx.x * BM;
    const int tid  = threadIdx.x;

    if (m0 < cnt) {
        const int n0   = blockIdx.y * BN;
        const int lane = tid & 31, wid = tid >> 5;
        const int wm = wid & 1, wn = wid >> 1;    // 2 m-warps x 4 n-warps
        const int g = lane >> 2, tg = lane & 3;

        const float* W = Wglob + (size_t)e * (size_t)KTOT * NLD;

        if (!IS_G2 && tid < BN) s_bias[tid] = bglob[(size_t)e * NLD + n0 + tid];

        // per-thread cp.async slots: A
        const float* asrc[4];
        uint32_t     adst[4];
        #pragma unroll
        for (int j = 0; j < 4; j++) {
            int idx = tid + 256 * j;              // 0..1023
            int r = idx >> 3, kq = idx & 7;
            int slot = base + m0 + r;
            if (slot > MAXROWS - 1) slot = MAXROWS - 1;
            if (IS_G2) asrc[j] = Aglob + (size_t)slot * ALDIM + kq * 4;
            else       asrc[j] = Aglob + (size_t)g_rowmap[slot] * ALDIM + kq * 4;
            adst[j] = smem_u32(As + r * LDA + kq * 4);
        }
        // per-thread cp.async slots: B
        const float* bsrc[4];
        uint32_t     bdst[4];
        #pragma unroll
        for (int j = 0; j < 4; j++) {
            int idx = tid + 256 * j;
            int k = idx >> 5, nq = idx & 31;
            bsrc[j] = W + (size_t)k * NLD + n0 + nq * 4;
            bdst[j] = smem_u32(Bs + k * LDB + nq * 4);
        }

        // ldmatrix A base addresses (mi = 0..3)
        uint32_t amat[4];
        {
            int sector = lane >> 3, rowin = lane & 7;
            #pragma unroll
            for (int mi = 0; mi < 4; mi++) {
                int rloc = wm * 64 + mi * 16 + (sector & 1) * 8 + rowin;
                int colb = (sector >> 1) * 4;
                amat[mi] = smem_u32(As + rloc * LDA + colb);
            }
        }

        float acc[4][4][4] = {};

        // prologue: prefetch chunks 0 and 1
        #pragma unroll
        for (int pc = 0; pc < ST - 1; pc++) {
            const uint32_t soa = (uint32_t)(pc * ABY * 4);
            const uint32_t sob = (uint32_t)(pc * BBY * 4);
            const int k0 = pc * BK;
            #pragma unroll
            for (int j = 0; j < 4; j++) CP16(adst[j] + soa, asrc[j] + k0);
            #pragma unroll
            for (int j = 0; j < 4; j++) CP16(bdst[j] + sob, bsrc[j] + (size_t)k0 * NLD);
            CP_COMMIT();
        }

        for (int c = 0; c < KCH; c++) {
            CP_WAIT1();          // chunk c resident
            __syncthreads();

            const int wb = (c + ST - 1) % ST;
            if (c + ST - 1 < KCH) {
                const uint32_t soa = (uint32_t)(wb * ABY * 4);
                const uint32_t sob = (uint32_t)(wb * BBY * 4);
                const int k0 = (c + ST - 1) * BK;
                #pragma unroll
                for (int j = 0; j < 4; j++) CP16(adst[j] + soa, asrc[j] + k0);
                #pragma unroll
                for (int j = 0; j < 4; j++) CP16(bdst[j] + sob, bsrc[j] + (size_t)k0 * NLD);
            }
            CP_COMMIT();

            const int buf = c % ST;
            const float* Bb = Bs + buf * BBY;
            const uint32_t aoff = (uint32_t)(buf * ABY * 4);

            #pragma unroll
            for (int ks = 0; ks < 4; ks++) {
                const int kc = ks * 8 + tg;
                uint32_t au[4][4], bu[4][2];
                #pragma unroll
                for (int mi = 0; mi < 4; mi++)
                    LDSM_X4(au[mi], amat[mi] + aoff + (uint32_t)(ks * 32));
                #pragma unroll
                for (int ni = 0; ni < 4; ni++) {
                    const int bn = wn * 32 + ni * 8 + g;
                    bu[ni][0] = __float_as_uint(Bb[kc * LDB + bn]);        // pre-tf32
                    bu[ni][1] = __float_as_uint(Bb[(kc + 4) * LDB + bn]);  // pre-tf32
                }
                #pragma unroll
                for (int mi = 0; mi < 4; mi++)
                    #pragma unroll
                    for (int ni = 0; ni < 4; ni++)
                        MMA_TF32(acc[mi][ni], au[mi], bu[ni]);
            }
        }
        CP_WAITALL();

        // ---------------- epilogue ----------------
        #pragma unroll
        for (int mi = 0; mi < 4; mi++) {
            #pragma unroll
            for (int half = 0; half < 2; half++) {
                const int rl = wm * 64 + mi * 16 + half * 8 + g;
                if ((m0 + rl) >= cnt) continue;
                const int slot = base + m0 + rl;
                if (IS_G2) {
                    float* orow = g_O + (size_t)slot * DIM + n0;
                    #pragma unroll
                    for (int ni = 0; ni < 4; ni++) {
                        const int cl = wn * 32 + ni * 8 + tg * 2;
                        float2 v;
                        v.x = acc[mi][ni][half * 2 + 0];
                        v.y = acc[mi][ni][half * 2 + 1];
                        *(float2*)(orow + cl) = v;
                    }
                } else {
                    float* hrow = g_H + (size_t)slot * HID + n0;
                    #pragma unroll
                    for (int ni = 0; ni < 4; ni++) {
                        const int cl = wn * 32 + ni * 8 + tg * 2;
                        float2 v;
                        v.x = tf32r(fmaxf(acc[mi][ni][half * 2 + 0] + s_bias[cl], 0.f));
                        v.y = tf32r(fmaxf(acc[mi][ni][half * 2 + 1] + s_bias[cl + 1], 0.f));
                        *(float2*)(hrow + cl) = v;
                    }
                }
            }
        }
    }

    // ---- GEMM1 tail: every CTA rounds its static chunk of W2 -> g_W2r ------
    if (!IS_G2) {
        // grid is (16, 32, 8) = 4096 CTAs; W2 = 8.39M float4 = 2048/CTA
        const size_t cta = (size_t)blockIdx.x +
                           16 * ((size_t)blockIdx.y + 32 * (size_t)blockIdx.z);
        const float4* src = (const float4*)W2src;
        float4*       dst = (float4*)g_W2r;
        const size_t b0 = cta * 2048;
        #pragma unroll
        for (int j = 0; j < 8; j++) {
            size_t idx = b0 + (size_t)j * 256 + tid;
            float4 v = src[idx];
            v.x = tf32r(v.x); v.y = tf32r(v.y); v.z = tf32r(v.z); v.w = tf32r(v.w);
            dst[idx] = v;
        }
    }
}

// ---------------- K5: combine out[t] = sum_k w_k * (o_k + b2[e_k]) ----------
__global__ void k_combine(const float* __restrict__ b2, float* __restrict__ out)
{
    int t = blockIdx.x;
    int d = threadIdx.x * 4;
    int e0 = g_tok_e[t * 2], e1 = g_tok_e[t * 2 + 1];
    float w0 = g_tok_w[t * 2], w1 = g_tok_w[t * 2 + 1];
    int s0 = g_tok_slot[t * 2], s1 = g_tok_slot[t * 2 + 1];

    float4 o0 = *(const float4*)(g_O + (size_t)s0 * DIM + d);
    float4 o1 = *(const float4*)(g_O + (size_t)s1 * DIM + d);
    float4 c0 = *(const float4*)(b2 + (size_t)e0 * DIM + d);
    float4 c1 = *(const float4*)(b2 + (size_t)e1 * DIM + d);

    float4 r;
    r.x = w0 * (o0.x + c0.x) + w1 * (o1.x + c1.x);
    r.y = w0 * (o0.y + c0.y) + w1 * (o1.y + c1.y);
    r.z = w0 * (o0.z + c0.z) + w1 * (o1.z + c1.z);
    r.w = w0 * (o0.w + c0.w) + w1 * (o1.w + c1.w);
    *(float4*)(out + (size_t)t * DIM + d) = r;
}

// ---------------- launch -----------------------------------------------------
extern "C" void kernel_launch(void* const* d_in, const int* in_sizes, int n_in,
                              void* d_out, int out_size)
{
    const float* u    = (const float*)d_in[0];
    const float* cent = (const float*)d_in[1];
    const float* bias = (const float*)d_in[2];
    const float* W1   = (const float*)d_in[3];
    const float* b1   = (const float*)d_in[4];
    const float* W2   = (const float*)d_in[5];
    const float* b2   = (const float*)d_in[6];
    float* out = (float*)d_out;

    float* maxvio_ptr;
    if (out_size > T_TOK * DIM) {
        maxvio_ptr = out + (size_t)T_TOK * DIM;
    } else {
        cudaGetSymbolAddress((void**)&maxvio_ptr, g_dummy);
    }
    float* uruf;  cudaGetSymbolAddress((void**)&uruf, g_U);
    float* hbuf;  cudaGetSymbolAddress((void**)&hbuf, g_H);
    float* w1r;   cudaGetSymbolAddress((void**)&w1r,  g_W1r);
    float* w2r;   cudaGetSymbolAddress((void**)&w2r,  g_W2r);

    // smem: 128 + 3*(128*36 + 32*136) floats = 27008 -> 108032 B
    const int SMEM = 27008 * 4;
    cudaFuncSetAttribute(k_gemm_mma<0>, cudaFuncAttributeMaxDynamicSharedMemorySize, SMEM);
    cudaFuncSetAttribute(k_gemm_mma<1>, cudaFuncAttributeMaxDynamicSharedMemorySize, SMEM);

    // prep covers u (0.52M float4) + W1 (8.39M float4) = 8.91M -> 34816 blocks
    const size_t PREP4 = ((size_t)T_TOK * DIM + W1ELEM) / 4;
    k_prep<<<(unsigned)((PREP4 + 255) / 256), 256>>>(u, W1);     // idx 0
    k_router<<<T_TOK, 256>>>(u, cent, bias);                     // idx 1
    k_offscatter<<<1, 1024>>>(maxvio_ptr);                       // idx 2
    k_gemm_mma<0><<<dim3(16, HID / 128, NEXP), 256, SMEM>>>(uruf, w1r, b1, W2);     // idx 3
    k_gemm_mma<1><<<dim3(16, DIM / 128, NEXP), 256, SMEM>>>(hbuf, w2r, b2, nullptr); // idx 4
    k_combine<<<T_TOK, 256>>>(b2, out);                          // idx 5
}

// round 12
// speedup vs baseline: 2.0206x; 1.7320x over previous
#include <cuda_runtime.h>
#include <cuda_fp16.h>
#include <cstdint>
#include <math.h>

#define T_TOK   2048
#define DIM     1024
#define NEXP    8
#define HID     4096
#define TOPK    2
#define MAXROWS (T_TOK * TOPK)   // 4096
#define W1ELEM  ((size_t)NEXP * DIM * HID)   // 33.55M
#define W2ELEM  ((size_t)NEXP * HID * DIM)

// ---------------- scratch (__device__ globals) -------------------------------
__device__ __half g_Hh[(size_t)MAXROWS * HID];   // 32 MB hidden acts (fp16)
__device__ __half g_Uh[(size_t)T_TOK * DIM];     // 4 MB fp16 inputs
__device__ __half g_W1h[W1ELEM];                 // 67 MB fp16 W1 [e][k][n]
__device__ __half g_W2h[W2ELEM];                 // 67 MB fp16 W2 [e][k][n]
__device__ float  g_O[(size_t)MAXROWS * DIM];    // 16 MB expert outputs (fp32)
__device__ int    g_rowmap[MAXROWS];
__device__ int    g_counts[NEXP];
__device__ int    g_offsets[NEXP + 1];
__device__ int    g_tok_e[T_TOK * TOPK];
__device__ float  g_tok_w[T_TOK * TOPK];
__device__ int    g_tok_slot[T_TOK * TOPK];
__device__ float  g_dummy[1];

// ---------------- helpers ----------------------------------------------------
__device__ __forceinline__ uint32_t smem_u32(const void* p) {
    uint32_t a;
    asm("{ .reg .u64 t; cvta.to.shared.u64 t, %1; cvt.u32.u64 %0, t; }"
        : "=r"(a) : "l"(p));
    return a;
}
__device__ __forceinline__ uint32_t packh2(float a, float b) {
    __half2 h = __floats2half2_rn(a, b);
    return *(uint32_t*)&h;
}

#define CP16(dst, src) \
    asm volatile("cp.async.cg.shared.global [%0], [%1], 16;" :: "r"(dst), "l"(src))
#define CP_COMMIT()  asm volatile("cp.async.commit_group;" ::: "memory")
#define CP_WAIT1()   asm volatile("cp.async.wait_group 1;" ::: "memory")
#define CP_WAITALL() asm volatile("cp.async.wait_all;" ::: "memory")

#define LDSM_X4(r, addr) \
    asm volatile("ldmatrix.sync.aligned.m8n8.x4.shared.b16 {%0,%1,%2,%3}, [%4];" \
        : "=r"((r)[0]), "=r"((r)[1]), "=r"((r)[2]), "=r"((r)[3]) : "r"(addr))

#define LDSM_X4_T(r, addr) \
    asm volatile("ldmatrix.sync.aligned.m8n8.x4.trans.shared.b16 {%0,%1,%2,%3}, [%4];" \
        : "=r"((r)[0]), "=r"((r)[1]), "=r"((r)[2]), "=r"((r)[3]) : "r"(addr))

#define MMA_F16(d, a, b) \
    asm volatile("mma.sync.aligned.m16n8k16.row.col.f32.f16.f16.f32 " \
        "{%0,%1,%2,%3}, {%4,%5,%6,%7}, {%8,%9}, {%0,%1,%2,%3};" \
        : "+f"((d)[0]), "+f"((d)[1]), "+f"((d)[2]), "+f"((d)[3]) \
        : "r"((a)[0]), "r"((a)[1]), "r"((a)[2]), "r"((a)[3]), \
          "r"((b)[0]), "r"((b)[1]))

// ---------------- K0: fp32 -> fp16 conversion of u, W1, W2; reset counters ---
__global__ void k_prep(const float* __restrict__ u,
                       const float* __restrict__ W1,
                       const float* __restrict__ W2)
{
    const size_t U8 = (size_t)T_TOK * DIM / 8;   // 262144
    const size_t W8 = W1ELEM / 8;                // 4194304
    size_t i = (size_t)blockIdx.x * blockDim.x + threadIdx.x;

    const float4* src = nullptr;
    uint4*        dst = nullptr;
    size_t j = 0;
    if (i < U8)                { src = (const float4*)u;  dst = (uint4*)g_Uh;  j = i; }
    else if (i < U8 + W8)      { src = (const float4*)W1; dst = (uint4*)g_W1h; j = i - U8; }
    else if (i < U8 + 2 * W8)  { src = (const float4*)W2; dst = (uint4*)g_W2h; j = i - U8 - W8; }

    if (src) {
        float4 a = src[2 * j], b = src[2 * j + 1];
        uint4 o;
        o.x = packh2(a.x, a.y);
        o.y = packh2(a.z, a.w);
        o.z = packh2(b.x, b.y);
        o.w = packh2(b.z, b.w);
        dst[j] = o;
    }
    if (blockIdx.x == 0 && threadIdx.x < NEXP) g_counts[threadIdx.x] = 0;
}

// ---------------- K1: router -------------------------------------------------
__global__ void k_router(const float* __restrict__ u,
                         const float* __restrict__ cent,
                         const float* __restrict__ bias)
{
    int t    = blockIdx.x;
    int warp = threadIdx.x >> 5;
    int lane = threadIdx.x & 31;

    const float* ur = u + (size_t)t * DIM;
    const float* cr = cent + (size_t)warp * DIM;

    float s = 0.f;
    #pragma unroll 8
    for (int i = lane; i < DIM; i += 32) s += ur[i] * cr[i];
    #pragma unroll
    for (int o = 16; o; o >>= 1) s += __shfl_xor_sync(0xffffffffu, s, o);

    __shared__ float sc[NEXP];
    if (lane == 0) sc[warp] = s + bias[warp];
    __syncthreads();

    if (threadIdx.x == 0) {
        float m = sc[0];
        #pragma unroll
        for (int e = 1; e < NEXP; e++) m = fmaxf(m, sc[e]);
        float p[NEXP];
        float den = 0.f;
        #pragma unroll
        for (int e = 0; e < NEXP; e++) { p[e] = __expf(sc[e] - m); den += p[e]; }

        int e0 = 0;
        #pragma unroll
        for (int e = 1; e < NEXP; e++) if (p[e] > p[e0]) e0 = e;
        int e1 = (e0 == 0) ? 1 : 0;
        #pragma unroll
        for (int e = 0; e < NEXP; e++) if (e != e0 && p[e] > p[e1]) e1 = e;

        float inv = 1.f / den;
        g_tok_e[t * 2 + 0] = e0;  g_tok_w[t * 2 + 0] = p[e0] * inv;
        g_tok_e[t * 2 + 1] = e1;  g_tok_w[t * 2 + 1] = p[e1] * inv;
        atomicAdd(&g_counts[e0], 1);
        atomicAdd(&g_counts[e1], 1);
    }
}

// ---------------- K2: fused offsets + maxvio + scatter (single block) --------
__global__ void k_offscatter(float* __restrict__ maxvio_out)
{
    __shared__ int s_off[NEXP];
    __shared__ int s_cur[NEXP];
    int tid = threadIdx.x;
    if (tid < NEXP) s_cur[tid] = 0;
    if (tid == 0) {
        int off = 0, mx = 0;
        #pragma unroll
        for (int e = 0; e < NEXP; e++) {
            s_off[e] = off;
            g_offsets[e] = off;
            int c = g_counts[e];
            off += c;
            if (c > mx) mx = c;
        }
        g_offsets[NEXP] = off;
        const float perfect = (float)(TOPK * T_TOK) / (float)NEXP;
        *maxvio_out = ((float)mx - perfect) / perfect;
    }
    __syncthreads();
    for (int t = tid; t < T_TOK; t += blockDim.x) {
        #pragma unroll
        for (int k = 0; k < TOPK; k++) {
            int e = g_tok_e[t * 2 + k];
            int slot = s_off[e] + atomicAdd(&s_cur[e], 1);
            g_rowmap[slot] = t;
            g_tok_slot[t * 2 + k] = slot;
        }
    }
}

// ---------------- fp16 mma.sync grouped GEMM ---------------------------------
// Block 128x128, BK=64 (halves), 3-stage cp.async, 8 warps (2m x 4n),
// warp tile 64x32 via mma.m16n8k16.f16 (fp32 acc).
// A [rows][K] fp16 via ldmatrix.x4; B [K][N] fp16 (natural weight layout)
// via ldmatrix.x4.trans. Per k16-step per warp: 4 LDSM + 2 LDSM.T + 16 MMA.
// IS_G2 == 0: g_Hh[slot] = fp16(relu(A @ W1h[e] + b1[e]))  (K=1024, N=4096)
// IS_G2 == 1: g_O[slot]  = A @ W2h[e]                       (K=4096, N=1024)
template<int IS_G2>
__global__ __launch_bounds__(256, 2) void k_gemm_f16(
    const __half* __restrict__ Aglob,
    const __half* __restrict__ Wglob,
    const float* __restrict__ bglob)
{
    constexpr int BM = 128, BN = 128, BK = 64, ST = 3;
    constexpr int LDA = BK + 8;               // 72 halves (row 144B; 16B-step 9 -> cf)
    constexpr int LDB = BN + 8;               // 136 halves (row 272B; 16B-step 17 -> cf)
    constexpr int NLD   = IS_G2 ? DIM : HID;
    constexpr int KTOT  = IS_G2 ? HID : DIM;
    constexpr int KCH   = KTOT / BK;
    constexpr int ALDIM = IS_G2 ? HID : DIM;
    constexpr int ASZ = BM * LDA * 2;         // 18432 B per A stage
    constexpr int BSZ = BK * LDB * 2;         // 17408 B per B stage
    constexpr int OFF_A = 512;
    constexpr int OFF_B = OFF_A + ST * ASZ;   // 55808

    extern __shared__ char smem[];
    float* s_bias = (float*)smem;             // 128 floats

    const int e    = blockIdx.z;
    const int base = g_offsets[e];
    const int cnt  = g_offsets[e + 1] - base;
    const int m0   = blockIdx.x * BM;
    if (m0 >= cnt) return;
    const int n0   = blockIdx.y * BN;

    const uint32_t sb = smem_u32(smem);
    const int tid  = threadIdx.x;
    const int lane = tid & 31, wid = tid >> 5;
    const int wm = wid & 1, wn = wid >> 1;    // 2 m-warps x 4 n-warps
    const int g = lane >> 2, tg = lane & 3;

    const __half* W = Wglob + (size_t)e * (size_t)KTOT * NLD;

    if (!IS_G2 && tid < BN) s_bias[tid] = bglob[(size_t)e * NLD + n0 + tid];

    // cp.async slots: A — 128 rows x 8 16B-units (8 halves) = 1024 -> 4/thread
    const __half* asrc[4];
    uint32_t      adst[4];
    #pragma unroll
    for (int j = 0; j < 4; j++) {
        int idx = tid + 256 * j;
        int r = idx >> 3, kq = idx & 7;
        int slot = base + m0 + r;
        if (slot > MAXROWS - 1) slot = MAXROWS - 1;
        if (IS_G2) asrc[j] = Aglob + (size_t)slot * ALDIM + kq * 8;
        else       asrc[j] = Aglob + (size_t)g_rowmap[slot] * ALDIM + kq * 8;
        adst[j] = sb + OFF_A + r * (LDA * 2) + kq * 16;
    }
    // cp.async slots: B — 64 k-rows x 16 16B-units = 1024 -> 4/thread
    const __half* bsrc[4];
    uint32_t      bdst[4];
    #pragma unroll
    for (int j = 0; j < 4; j++) {
        int idx = tid + 256 * j;
        int k = idx >> 4, nq = idx & 15;
        bsrc[j] = W + (size_t)k * NLD + n0 + nq * 8;
        bdst[j] = sb + OFF_B + k * (LDB * 2) + nq * 16;
    }

    // ldmatrix A bases (mi = 0..3): matrices (m0,k0),(m8,k0),(m0,k8),(m8,k8)
    uint32_t amat[4];
    {
        int sector = lane >> 3, rowin = lane & 7;
        #pragma unroll
        for (int mi = 0; mi < 4; mi++) {
            int rloc = wm * 64 + mi * 16 + (sector & 1) * 8 + rowin;
            amat[mi] = sb + OFF_A + rloc * (LDA * 2) + (sector >> 1) * 16;
        }
    }
    // ldmatrix.trans B bases (n2 = 0..1, each n16): matrices
    // (k0,n0),(k8,n0),(k0,n8),(k8,n8) -> regs {b_n0k0-7, b_n0k8-15, b_n8...}
    uint32_t bmat[2];
    {
        int sector = lane >> 3, rowin = lane & 7;
        #pragma unroll
        for (int n2 = 0; n2 < 2; n2++) {
            int krow = (sector & 1) * 8 + rowin;
            int ncol = wn * 32 + n2 * 16 + (sector >> 1) * 8;
            bmat[n2] = sb + OFF_B + krow * (LDB * 2) + ncol * 2;
        }
    }

    float acc[4][4][4] = {};

    // prologue: prefetch chunks 0 and 1
    #pragma unroll
    for (int pc = 0; pc < ST - 1; pc++) {
        const int k0 = pc * BK;
        #pragma unroll
        for (int j = 0; j < 4; j++) CP16(adst[j] + pc * ASZ, asrc[j] + k0);
        #pragma unroll
        for (int j = 0; j < 4; j++) CP16(bdst[j] + pc * BSZ, bsrc[j] + (size_t)k0 * NLD);
        CP_COMMIT();
    }

    for (int c = 0; c < KCH; c++) {
        CP_WAIT1();
        __syncthreads();

        const int wb = (c + ST - 1) % ST;
        if (c + ST - 1 < KCH) {
            const int k0 = (c + ST - 1) * BK;
            #pragma unroll
            for (int j = 0; j < 4; j++) CP16(adst[j] + wb * ASZ, asrc[j] + k0);
            #pragma unroll
            for (int j = 0; j < 4; j++) CP16(bdst[j] + wb * BSZ, bsrc[j] + (size_t)k0 * NLD);
        }
        CP_COMMIT();

        const int buf = c % ST;
        const uint32_t aoff = (uint32_t)(buf * ASZ);
        const uint32_t boff = (uint32_t)(buf * BSZ);

        #pragma unroll
        for (int ks = 0; ks < 4; ks++) {        // 4 x k16 per BK=64 chunk
            uint32_t au[4][4], br[2][4];
            #pragma unroll
            for (int mi = 0; mi < 4; mi++)
                LDSM_X4(au[mi], amat[mi] + aoff + (uint32_t)(ks * 32));      // +16 halves
            #pragma unroll
            for (int n2 = 0; n2 < 2; n2++)
                LDSM_X4_T(br[n2], bmat[n2] + boff + (uint32_t)(ks * 16 * LDB * 2));
            #pragma unroll
            for (int mi = 0; mi < 4; mi++)
                #pragma unroll
                for (int ni = 0; ni < 4; ni++)
                    MMA_F16(acc[mi][ni], au[mi], &br[ni >> 1][(ni & 1) * 2]);
        }
    }
    CP_WAITALL();

    // ---------------- epilogue ----------------
    #pragma unroll
    for (int mi = 0; mi < 4; mi++) {
        #pragma unroll
        for (int half = 0; half < 2; half++) {
            const int rl = wm * 64 + mi * 16 + half * 8 + g;
            if ((m0 + rl) >= cnt) continue;
            const int slot = base + m0 + rl;
            if (IS_G2) {
                float* orow = g_O + (size_t)slot * DIM + n0;
                #pragma unroll
                for (int ni = 0; ni < 4; ni++) {
                    const int cl = wn * 32 + ni * 8 + tg * 2;
                    float2 v;
                    v.x = acc[mi][ni][half * 2 + 0];
                    v.y = acc[mi][ni][half * 2 + 1];
                    *(float2*)(orow + cl) = v;
                }
            } else {
                __half* hrow = g_Hh + (size_t)slot * HID + n0;
                #pragma unroll
                for (int ni = 0; ni < 4; ni++) {
                    const int cl = wn * 32 + ni * 8 + tg * 2;
                    float vx = fmaxf(acc[mi][ni][half * 2 + 0] + s_bias[cl], 0.f);
                    float vy = fmaxf(acc[mi][ni][half * 2 + 1] + s_bias[cl + 1], 0.f);
                    *(__half2*)(hrow + cl) = __floats2half2_rn(vx, vy);
                }
            }
        }
    }
}

// ---------------- K5: combine out[t] = sum_k w_k * (o_k + b2[e_k]) ----------
__global__ void k_combine(const float* __restrict__ b2, float* __restrict__ out)
{
    int t = blockIdx.x;
    int d = threadIdx.x * 4;
    int e0 = g_tok_e[t * 2], e1 = g_tok_e[t * 2 + 1];
    float w0 = g_tok_w[t * 2], w1 = g_tok_w[t * 2 + 1];
    int s0 = g_tok_slot[t * 2], s1 = g_tok_slot[t * 2 + 1];

    float4 o0 = *(const float4*)(g_O + (size_t)s0 * DIM + d);
    float4 o1 = *(const float4*)(g_O + (size_t)s1 * DIM + d);
    float4 c0 = *(const float4*)(b2 + (size_t)e0 * DIM + d);
    float4 c1 = *(const float4*)(b2 + (size_t)e1 * DIM + d);

    float4 r;
    r.x = w0 * (o0.x + c0.x) + w1 * (o1.x + c1.x);
    r.y = w0 * (o0.y + c0.y) + w1 * (o1.y + c1.y);
    r.z = w0 * (o0.z + c0.z) + w1 * (o1.z + c1.z);
    r.w = w0 * (o0.w + c0.w) + w1 * (o1.w + c1.w);
    *(float4*)(out + (size_t)t * DIM + d) = r;
}

// ---------------- launch -----------------------------------------------------
extern "C" void kernel_launch(void* const* d_in, const int* in_sizes, int n_in,
                              void* d_out, int out_size)
{
    const float* u    = (const float*)d_in[0];
    const float* cent = (const float*)d_in[1];
    const float* bias = (const float*)d_in[2];
    const float* W1   = (const float*)d_in[3];
    const float* b1   = (const float*)d_in[4];
    const float* W2   = (const float*)d_in[5];
    const float* b2   = (const float*)d_in[6];
    float* out = (float*)d_out;

    float* maxvio_ptr;
    if (out_size > T_TOK * DIM) {
        maxvio_ptr = out + (size_t)T_TOK * DIM;
    } else {
        cudaGetSymbolAddress((void**)&maxvio_ptr, g_dummy);
    }
    __half* uh;   cudaGetSymbolAddress((void**)&uh,  g_Uh);
    __half* hh;   cudaGetSymbolAddress((void**)&hh,  g_Hh);
    __half* w1h;  cudaGetSymbolAddress((void**)&w1h, g_W1h);
    __half* w2h;  cudaGetSymbolAddress((void**)&w2h, g_W2h);

    // dyn smem: 512 (bias) + 3*18432 (A) + 3*17408 (B) = 108032 B
    const int SMEM = 108032;
    cudaFuncSetAttribute(k_gemm_f16<0>, cudaFuncAttributeMaxDynamicSharedMemorySize, SMEM);
    cudaFuncSetAttribute(k_gemm_f16<1>, cudaFuncAttributeMaxDynamicSharedMemorySize, SMEM);

    const size_t PREP = (size_t)T_TOK * DIM / 8 + 2 * (W1ELEM / 8);  // 8.65M threads
    k_prep<<<(unsigned)((PREP + 255) / 256), 256>>>(u, W1, W2);      // idx 0
    k_router<<<T_TOK, 256>>>(u, cent, bias);                         // idx 1
    k_offscatter<<<1, 1024>>>(maxvio_ptr);                           // idx 2
    k_gemm_f16<0><<<dim3(16, HID / 128, NEXP), 256, SMEM>>>(uh, w1h, b1);  // idx 3
    k_gemm_f16<1><<<dim3(16, DIM / 128, NEXP), 256, SMEM>>>(hh, w2h, b2);  // idx 4
    k_combine<<<T_TOK, 256>>>(b2, out);                              // idx 5
}

// round 13
// speedup vs baseline: 2.0297x; 1.0045x over previous
#include <cuda_runtime.h>
#include <cuda_fp16.h>
#include <cstdint>
#include <math.h>

#define T_TOK   2048
#define DIM     1024
#define NEXP    8
#define HID     4096
#define TOPK    2
#define MAXROWS (T_TOK * TOPK)   // 4096
#define W1ELEM  ((size_t)NEXP * DIM * HID)   // 33.55M
#define W2ELEM  ((size_t)NEXP * HID * DIM)

// ---------------- scratch (__device__ globals) -------------------------------
__device__ __half g_Hh[(size_t)MAXROWS * HID];   // 32 MB hidden acts (fp16)
__device__ __half g_Uh[(size_t)T_TOK * DIM];     // 4 MB fp16 inputs
__device__ __half g_W1h[W1ELEM];                 // 67 MB fp16 W1 [e][k][n]
__device__ __half g_W2h[W2ELEM];                 // 67 MB fp16 W2 [e][k][n]
__device__ float  g_O[(size_t)MAXROWS * DIM];    // 16 MB expert outputs (K-half 0)
__device__ float  g_O2[(size_t)MAXROWS * DIM];   // 16 MB expert outputs (K-half 1)
__device__ int    g_rowmap[MAXROWS];
__device__ int    g_counts[NEXP];
__device__ int    g_offsets[NEXP + 1];
__device__ int    g_tok_e[T_TOK * TOPK];
__device__ float  g_tok_w[T_TOK * TOPK];
__device__ int    g_tok_slot[T_TOK * TOPK];
__device__ float  g_dummy[1];

// ---------------- helpers ----------------------------------------------------
__device__ __forceinline__ uint32_t smem_u32(const void* p) {
    uint32_t a;
    asm("{ .reg .u64 t; cvta.to.shared.u64 t, %1; cvt.u32.u64 %0, t; }"
        : "=r"(a) : "l"(p));
    return a;
}
__device__ __forceinline__ uint32_t packh2(float a, float b) {
    __half2 h = __floats2half2_rn(a, b);
    return *(uint32_t*)&h;
}

#define CP16(dst, src) \
    asm volatile("cp.async.cg.shared.global [%0], [%1], 16;" :: "r"(dst), "l"(src))
#define CP_COMMIT()  asm volatile("cp.async.commit_group;" ::: "memory")
#define CP_WAIT1()   asm volatile("cp.async.wait_group 1;" ::: "memory")
#define CP_WAITALL() asm volatile("cp.async.wait_all;" ::: "memory")

#define LDSM_X4(r, addr) \
    asm volatile("ldmatrix.sync.aligned.m8n8.x4.shared.b16 {%0,%1,%2,%3}, [%4];" \
        : "=r"((r)[0]), "=r"((r)[1]), "=r"((r)[2]), "=r"((r)[3]) : "r"(addr))

#define LDSM_X4_T(r, addr) \
    asm volatile("ldmatrix.sync.aligned.m8n8.x4.trans.shared.b16 {%0,%1,%2,%3}, [%4];" \
        : "=r"((r)[0]), "=r"((r)[1]), "=r"((r)[2]), "=r"((r)[3]) : "r"(addr))

#define MMA_F16(d, a, b) \
    asm volatile("mma.sync.aligned.m16n8k16.row.col.f32.f16.f16.f32 " \
        "{%0,%1,%2,%3}, {%4,%5,%6,%7}, {%8,%9}, {%0,%1,%2,%3};" \
        : "+f"((d)[0]), "+f"((d)[1]), "+f"((d)[2]), "+f"((d)[3]) \
        : "r"((a)[0]), "r"((a)[1]), "r"((a)[2]), "r"((a)[3]), \
          "r"((b)[0]), "r"((b)[1]))

// ---------------- K0: fp32 -> fp16 of u and W1; reset counters ---------------
__global__ void k_prep(const float* __restrict__ u, const float* __restrict__ W1)
{
    const size_t U8 = (size_t)T_TOK * DIM / 8;   // 262144
    const size_t W8 = W1ELEM / 8;                // 4194304
    size_t i = (size_t)blockIdx.x * blockDim.x + threadIdx.x;

    const float4* src = nullptr;
    uint4*        dst = nullptr;
    size_t j = 0;
    if (i < U8)           { src = (const float4*)u;  dst = (uint4*)g_Uh;  j = i; }
    else if (i < U8 + W8) { src = (const float4*)W1; dst = (uint4*)g_W1h; j = i - U8; }

    if (src) {
        float4 a = src[2 * j], b = src[2 * j + 1];
        uint4 o;
        o.x = packh2(a.x, a.y);
        o.y = packh2(a.z, a.w);
        o.z = packh2(b.x, b.y);
        o.w = packh2(b.z, b.w);
        dst[j] = o;
    }
    if (blockIdx.x == 0 && threadIdx.x < NEXP) g_counts[threadIdx.x] = 0;
}

// ---------------- K1: router -------------------------------------------------
__global__ void k_router(const float* __restrict__ u,
                         const float* __restrict__ cent,
                         const float* __restrict__ bias)
{
    int t    = blockIdx.x;
    int warp = threadIdx.x >> 5;
    int lane = threadIdx.x & 31;

    const float* ur = u + (size_t)t * DIM;
    const float* cr = cent + (size_t)warp * DIM;

    float s = 0.f;
    #pragma unroll 8
    for (int i = lane; i < DIM; i += 32) s += ur[i] * cr[i];
    #pragma unroll
    for (int o = 16; o; o >>= 1) s += __shfl_xor_sync(0xffffffffu, s, o);

    __shared__ float sc[NEXP];
    if (lane == 0) sc[warp] = s + bias[warp];
    __syncthreads();

    if (threadIdx.x == 0) {
        float m = sc[0];
        #pragma unroll
        for (int e = 1; e < NEXP; e++) m = fmaxf(m, sc[e]);
        float p[NEXP];
        float den = 0.f;
        #pragma unroll
        for (int e = 0; e < NEXP; e++) { p[e] = __expf(sc[e] - m); den += p[e]; }

        int e0 = 0;
        #pragma unroll
        for (int e = 1; e < NEXP; e++) if (p[e] > p[e0]) e0 = e;
        int e1 = (e0 == 0) ? 1 : 0;
        #pragma unroll
        for (int e = 0; e < NEXP; e++) if (e != e0 && p[e] > p[e1]) e1 = e;

        float inv = 1.f / den;
        g_tok_e[t * 2 + 0] = e0;  g_tok_w[t * 2 + 0] = p[e0] * inv;
        g_tok_e[t * 2 + 1] = e1;  g_tok_w[t * 2 + 1] = p[e1] * inv;
        atomicAdd(&g_counts[e0], 1);
        atomicAdd(&g_counts[e1], 1);
    }
}

// ---------------- K2: fused offsets + maxvio + scatter (single block) --------
__global__ void k_offscatter(float* __restrict__ maxvio_out)
{
    __shared__ int s_off[NEXP];
    __shared__ int s_cur[NEXP];
    int tid = threadIdx.x;
    if (tid < NEXP) s_cur[tid] = 0;
    if (tid == 0) {
        int off = 0, mx = 0;
        #pragma unroll
        for (int e = 0; e < NEXP; e++) {
            s_off[e] = off;
            g_offsets[e] = off;
            int c = g_counts[e];
            off += c;
            if (c > mx) mx = c;
        }
        g_offsets[NEXP] = off;
        const float perfect = (float)(TOPK * T_TOK) / (float)NEXP;
        *maxvio_out = ((float)mx - perfect) / perfect;
    }
    __syncthreads();
    for (int t = tid; t < T_TOK; t += blockDim.x) {
        #pragma unroll
        for (int k = 0; k < TOPK; k++) {
            int e = g_tok_e[t * 2 + k];
            int slot = s_off[e] + atomicAdd(&s_cur[e], 1);
            g_rowmap[slot] = t;
            g_tok_slot[t * 2 + k] = slot;
        }
    }
}

// ---------------- fp16 mma.sync grouped GEMM ---------------------------------
// Block 128x128, BK=64, 3-stage cp.async, 8 warps (2m x 4n), warp tile 64x32.
// IS_G2 == 0: g_Hh[slot] = fp16(relu(A @ W1h[e] + b1[e]))  (K=1024; grid.y = n-tile)
//             + every CTA converts a static 8192-half chunk of W2 -> g_W2h.
// IS_G2 == 1: K split 2: grid.y packs (n-tile 0..7, khalf 0..1);
//             khalf 0 -> g_O, khalf 1 -> g_O2 (summed in k_combine).
template<int IS_G2>
__global__ __launch_bounds__(256, 2) void k_gemm_f16(
    const __half* __restrict__ Aglob,
    const __half* __restrict__ Wglob,
    const float* __restrict__ bglob,
    const float* __restrict__ W2src)
{
    constexpr int BM = 128, BN = 128, BK = 64, ST = 3;
    constexpr int LDA = BK + 8;               // 72 halves
    constexpr int LDB = BN + 8;               // 136 halves
    constexpr int NLD   = IS_G2 ? DIM : HID;
    constexpr int KTOT  = IS_G2 ? HID : DIM;
    constexpr int KCH   = IS_G2 ? (HID / 2 / BK) : (DIM / BK);   // 32 : 16
    constexpr int ALDIM = IS_G2 ? HID : DIM;
    constexpr int ASZ = BM * LDA * 2;         // 18432 B per A stage
    constexpr int BSZ = BK * LDB * 2;         // 17408 B per B stage
    constexpr int OFF_A = 512;
    constexpr int OFF_B = OFF_A + ST * ASZ;

    extern __shared__ char smem[];
    float* s_bias = (float*)smem;

    const int e    = blockIdx.z;
    const int base = g_offsets[e];
    const int cnt  = g_offsets[e + 1] - base;
    const int m0   = blockIdx.x * BM;
    const int tid  = threadIdx.x;

    if (m0 < cnt) {
        const int n0 = (IS_G2 ? (blockIdx.y & 7) : blockIdx.y) * BN;
        const int kbase = IS_G2 ? ((blockIdx.y >> 3) * (HID / 2)) : 0;

        const uint32_t sb = smem_u32(smem);
        const int lane = tid & 31, wid = tid >> 5;
        const int wm = wid & 1, wn = wid >> 1;
        const int g = lane >> 2, tg = lane & 3;

        const __half* W = Wglob + (size_t)e * (size_t)KTOT * NLD;

        if (!IS_G2 && tid < BN) s_bias[tid] = bglob[(size_t)e * NLD + n0 + tid];

        // cp.async slots: A — 128 rows x 8 16B-units = 1024 -> 4/thread
        const __half* asrc[4];
        uint32_t      adst[4];
        #pragma unroll
        for (int j = 0; j < 4; j++) {
            int idx = tid + 256 * j;
            int r = idx >> 3, kq = idx & 7;
            int slot = base + m0 + r;
            if (slot > MAXROWS - 1) slot = MAXROWS - 1;
            if (IS_G2) asrc[j] = Aglob + (size_t)slot * ALDIM + kbase + kq * 8;
            else       asrc[j] = Aglob + (size_t)g_rowmap[slot] * ALDIM + kq * 8;
            adst[j] = sb + OFF_A + r * (LDA * 2) + kq * 16;
        }
        // cp.async slots: B — 64 k-rows x 16 16B-units = 1024 -> 4/thread
        const __half* bsrc[4];
        uint32_t      bdst[4];
        #pragma unroll
        for (int j = 0; j < 4; j++) {
            int idx = tid + 256 * j;
            int k = idx >> 4, nq = idx & 15;
            bsrc[j] = W + (size_t)(kbase + k) * NLD + n0 + nq * 8;
            bdst[j] = sb + OFF_B + k * (LDB * 2) + nq * 16;
        }

        // ldmatrix A bases
        uint32_t amat[4];
        {
            int sector = lane >> 3, rowin = lane & 7;
            #pragma unroll
            for (int mi = 0; mi < 4; mi++) {
                int rloc = wm * 64 + mi * 16 + (sector & 1) * 8 + rowin;
                amat[mi] = sb + OFF_A + rloc * (LDA * 2) + (sector >> 1) * 16;
            }
        }
        // ldmatrix.trans B bases
        uint32_t bmat[2];
        {
            int sector = lane >> 3, rowin = lane & 7;
            #pragma unroll
            for (int n2 = 0; n2 < 2; n2++) {
                int krow = (sector & 1) * 8 + rowin;
                int ncol = wn * 32 + n2 * 16 + (sector >> 1) * 8;
                bmat[n2] = sb + OFF_B + krow * (LDB * 2) + ncol * 2;
            }
        }

        float acc[4][4][4] = {};

        // prologue: prefetch chunks 0 and 1
        #pragma unroll
        for (int pc = 0; pc < ST - 1; pc++) {
            const int k0 = pc * BK;
            #pragma unroll
            for (int j = 0; j < 4; j++) CP16(adst[j] + pc * ASZ, asrc[j] + k0);
            #pragma unroll
            for (int j = 0; j < 4; j++) CP16(bdst[j] + pc * BSZ, bsrc[j] + (size_t)k0 * NLD);
            CP_COMMIT();
        }

        for (int c = 0; c < KCH; c++) {
            CP_WAIT1();
            __syncthreads();

            const int wb = (c + ST - 1) % ST;
            if (c + ST - 1 < KCH) {
                const int k0 = (c + ST - 1) * BK;
                #pragma unroll
                for (int j = 0; j < 4; j++) CP16(adst[j] + wb * ASZ, asrc[j] + k0);
                #pragma unroll
                for (int j = 0; j < 4; j++) CP16(bdst[j] + wb * BSZ, bsrc[j] + (size_t)k0 * NLD);
            }
            CP_COMMIT();

            const int buf = c % ST;
            const uint32_t aoff = (uint32_t)(buf * ASZ);
            const uint32_t boff = (uint32_t)(buf * BSZ);

            #pragma unroll
            for (int ks = 0; ks < 4; ks++) {
                uint32_t au[4][4], br[2][4];
                #pragma unroll
                for (int mi = 0; mi < 4; mi++)
                    LDSM_X4(au[mi], amat[mi] + aoff + (uint32_t)(ks * 32));
                #pragma unroll
                for (int n2 = 0; n2 < 2; n2++)
                    LDSM_X4_T(br[n2], bmat[n2] + boff + (uint32_t)(ks * 16 * LDB * 2));
                #pragma unroll
                for (int mi = 0; mi < 4; mi++)
                    #pragma unroll
                    for (int ni = 0; ni < 4; ni++)
                        MMA_F16(acc[mi][ni], au[mi], &br[ni >> 1][(ni & 1) * 2]);
            }
        }
        CP_WAITALL();

        // ---------------- epilogue ----------------
        float* Obuf = (IS_G2 && (blockIdx.y >> 3)) ? g_O2 : g_O;
        #pragma unroll
        for (int mi = 0; mi < 4; mi++) {
            #pragma unroll
            for (int half = 0; half < 2; half++) {
                const int rl = wm * 64 + mi * 16 + half * 8 + g;
                if ((m0 + rl) >= cnt) continue;
                const int slot = base + m0 + rl;
                if (IS_G2) {
                    float* orow = Obuf + (size_t)slot * DIM + n0;
                    #pragma unroll
                    for (int ni = 0; ni < 4; ni++) {
                        const int cl = wn * 32 + ni * 8 + tg * 2;
                        float2 v;
                        v.x = acc[mi][ni][half * 2 + 0];
                        v.y = acc[mi][ni][half * 2 + 1];
                        *(float2*)(orow + cl) = v;
                    }
                } else {
                    __half* hrow = g_Hh + (size_t)slot * HID + n0;
                    #pragma unroll
                    for (int ni = 0; ni < 4; ni++) {
                        const int cl = wn * 32 + ni * 8 + tg * 2;
                        float vx = fmaxf(acc[mi][ni][half * 2 + 0] + s_bias[cl], 0.f);
                        float vy = fmaxf(acc[mi][ni][half * 2 + 1] + s_bias[cl + 1], 0.f);
                        *(__half2*)(hrow + cl) = __floats2half2_rn(vx, vy);
                    }
                }
            }
        }
    }

    // ---- GEMM1 tail: every CTA converts its static chunk of W2 -> g_W2h ----
    if (!IS_G2) {
        // grid (16, 32, 8) = 4096 CTAs; W2 = 4.19M uint4 -> 1024 uint4/CTA
        const size_t cta = (size_t)blockIdx.x +
                           16 * ((size_t)blockIdx.y + 32 * (size_t)blockIdx.z);
        const float4* src = (const float4*)W2src;
        uint4*        dst = (uint4*)g_W2h;
        const size_t b0 = cta * 1024;
        #pragma unroll
        for (int j = 0; j < 4; j++) {
            size_t idx = b0 + (size_t)j * 256 + tid;
            float4 a = src[2 * idx], b = src[2 * idx + 1];
            uint4 o;
            o.x = packh2(a.x, a.y);
            o.y = packh2(a.z, a.w);
            o.z = packh2(b.x, b.y);
            o.w = packh2(b.z, b.w);
            dst[idx] = o;
        }
    }
}

// ---------------- K5: combine out[t] = sum_k w_k * (oA_k + oB_k + b2[e_k]) ---
__global__ void k_combine(const float* __restrict__ b2, float* __restrict__ out)
{
    int t = blockIdx.x;
    int d = threadIdx.x * 4;
    int e0 = g_tok_e[t * 2], e1 = g_tok_e[t * 2 + 1];
    float w0 = g_tok_w[t * 2], w1 = g_tok_w[t * 2 + 1];
    int s0 = g_tok_slot[t * 2], s1 = g_tok_slot[t * 2 + 1];

    float4 a0 = *(const float4*)(g_O  + (size_t)s0 * DIM + d);
    float4 b0 = *(const float4*)(g_O2 + (size_t)s0 * DIM + d);
    float4 a1 = *(const float4*)(g_O  + (size_t)s1 * DIM + d);
    float4 b1v = *(const float4*)(g_O2 + (size_t)s1 * DIM + d);
    float4 c0 = *(const float4*)(b2 + (size_t)e0 * DIM + d);
    float4 c1 = *(const float4*)(b2 + (size_t)e1 * DIM + d);

    float4 r;
    r.x = w0 * (a0.x + b0.x + c0.x) + w1 * (a1.x + b1v.x + c1.x);
    r.y = w0 * (a0.y + b0.y + c0.y) + w1 * (a1.y + b1v.y + c1.y);
    r.z = w0 * (a0.z + b0.z + c0.z) + w1 * (a1.z + b1v.z + c1.z);
    r.w = w0 * (a0.w + b0.w + c0.w) + w1 * (a1.w + b1v.w + c1.w);
    *(float4*)(out + (size_t)t * DIM + d) = r;
}

// ---------------- launch -----------------------------------------------------
extern "C" void kernel_launch(void* const* d_in, const int* in_sizes, int n_in,
                              void* d_out, int out_size)
{
    const float* u    = (const float*)d_in[0];
    const float* cent = (const float*)d_in[1];
    const float* bias = (const float*)d_in[2];
    const float* W1   = (const float*)d_in[3];
    const float* b1   = (const float*)d_in[4];
    const float* W2   = (const float*)d_in[5];
    const float* b2   = (const float*)d_in[6];
    float* out = (float*)d_out;

    float* maxvio_ptr;
    if (out_size > T_TOK * DIM) {
        maxvio_ptr = out + (size_t)T_TOK * DIM;
    } else {
        cudaGetSymbolAddress((void**)&maxvio_ptr, g_dummy);
    }
    __half* uh;   cudaGetSymbolAddress((void**)&uh,  g_Uh);
    __half* hh;   cudaGetSymbolAddress((void**)&hh,  g_Hh);
    __half* w1h;  cudaGetSymbolAddress((void**)&w1h, g_W1h);
    __half* w2h;  cudaGetSymbolAddress((void**)&w2h, g_W2h);

    const int SMEM = 512 + 3 * 18432 + 3 * 17408;   // 108032 B
    cudaFuncSetAttribute(k_gemm_f16<0>, cudaFuncAttributeMaxDynamicSharedMemorySize, SMEM);
    cudaFuncSetAttribute(k_gemm_f16<1>, cudaFuncAttributeMaxDynamicSharedMemorySize, SMEM);

    const size_t PREP = (size_t)T_TOK * DIM / 8 + W1ELEM / 8;        // 4.46M threads
    k_prep<<<(unsigned)((PREP + 255) / 256), 256>>>(u, W1);          // idx 0
    k_router<<<T_TOK, 256>>>(u, cent, bias);                         // idx 1
    k_offscatter<<<1, 1024>>>(maxvio_ptr);                           // idx 2
    // gemm1: grid.y = 32 n-tiles; also converts W2 in its tail
    k_gemm_f16<0><<<dim3(16, HID / 128, NEXP), 256, SMEM>>>(uh, w1h, b1, W2);      // idx 3
    // gemm2: grid.y packs (8 n-tiles, 2 K-halves)
    k_gemm_f16<1><<<dim3(16, 16, NEXP), 256, SMEM>>>(hh, w2h, b2, nullptr);        // idx 4
    k_combine<<<T_TOK, 256>>>(b2, out);                              // idx 5
}